// round 15
// baseline (speedup 1.0000x reference)
#include <cuda_runtime.h>
#include <cuda_bf16.h>
#include <math.h>

#define NEP 256
#define NS  32
#define DIN 512
#define DF  512
#define T   1026
#define TT  513

#define LOG_2PIE 2.8378770664093453f

// K geometry for the logvar GEMM: K=1026 -> 513 k-pairs -> pad to 544 (17 chunks of 32)
#define LV_KP   544
#define LV_NPAD 1152   // 18 tiles of 64

// pair-GEMM K geometry: K = 4*1026 = 4104 -> 2052 pairs -> pad to 2080 (65 chunks of 32)
#define PK_STRIDE 2080
#define PK_CHUNKS 65
#define PK_SLICES 9

// -------- device scratch (no allocations allowed) --------
__device__ float g_mu [2][NEP][T];   // z (mu)
__device__ float g_Hpart[18][512];   // per-Ntile partial sums of lv per row (row = set*256+e)
__device__ float g_Mpart[18][512];   // per-Ntile partial sums of m^2*exp(-lv) per row
__device__ float g_spart[PK_SLICES][NEP][NEP]; // pairwise score partials per K-slice

// bf16 split operands. Inputs: [set][8192 rows][256 k-pair words] (K contiguous)
__device__ __align__(16) unsigned g_ihi[2][8192 * 256];
__device__ __align__(16) unsigned g_ilo[2][8192 * 256];
// W_fe split, k-pair interleaved: word (k2, n) holds halves (k=2*k2, 2*k2+1) of column n
__device__ __align__(16) unsigned g_wphi[256 * 512];
__device__ __align__(16) unsigned g_wplo[256 * 512];
// z split: [512 rows (set*256+e)][544 k-pair words]; pad never written (zero-init)
__device__ __align__(16) unsigned g_zhi[512 * LV_KP];
__device__ __align__(16) unsigned g_zlo[512 * LV_KP];
// W_lv split (padded)
__device__ __align__(16) unsigned g_wlvh[LV_KP * LV_NPAD];
__device__ __align__(16) unsigned g_wlvl[LV_KP * LV_NPAD];
// pairwise feature rows, bf16 split, k = 4*n + f (f=0..3), pad zero-init
__device__ __align__(16) unsigned g_pAhi[NEP * PK_STRIDE];
__device__ __align__(16) unsigned g_pAlo[NEP * PK_STRIDE];
__device__ __align__(16) unsigned g_pBhi[NEP * PK_STRIDE];
__device__ __align__(16) unsigned g_pBlo[NEP * PK_STRIDE];

// ============================================================
__device__ __forceinline__ void split1(float x, unsigned short& h, unsigned short& l)
{
    __nv_bfloat16 bh = __float2bfloat16(x);
    float r = x - __bfloat162float(bh);
    __nv_bfloat16 bl = __float2bfloat16(r);
    h = __bfloat16_as_ushort(bh);
    l = __bfloat16_as_ushort(bl);
}

__device__ __forceinline__ unsigned splitpair(float x0, float x1, unsigned& lo)
{
    unsigned short h0, l0, h1, l1;
    split1(x0, h0, l0);
    split1(x1, h1, l1);
    lo = (unsigned)l0 | ((unsigned)l1 << 16);
    return (unsigned)h0 | ((unsigned)h1 << 16);
}

__device__ __forceinline__ void cp16(unsigned saddr, const void* g)
{
    asm volatile("cp.async.cg.shared.global [%0], [%1], 16;\n" :: "r"(saddr), "l"(g));
}
__device__ __forceinline__ unsigned s2u(const void* p)
{
    return (unsigned)__cvta_generic_to_shared(p);
}
__device__ __forceinline__ void ldsm4(unsigned* r, unsigned addr)
{
    asm volatile("ldmatrix.sync.aligned.m8n8.x4.shared.b16 {%0,%1,%2,%3}, [%4];"
                 : "=r"(r[0]), "=r"(r[1]), "=r"(r[2]), "=r"(r[3]) : "r"(addr));
}

// ============================================================
// merged prep, 4x-vectorized (round-11 proven config)
// ============================================================
__global__ void k_prep(const float* __restrict__ trin, const float* __restrict__ tein,
                       const float* __restrict__ Wfe, const float* __restrict__ Wlv,
                       const float* __restrict__ trtg, const float* __restrict__ tetg)
{
    const int b = blockIdx.x;
    const int tid = threadIdx.x;

    if (b < 4096) {
        const int set = b >> 11;
        const unsigned w0 = ((unsigned)(b & 2047) * 256 + tid) * 4;
        const float4* src = (const float4*)(set ? tein : trin);
        float4 v0 = src[w0 >> 1];
        float4 v1 = src[(w0 >> 1) + 1];
        unsigned hi0, hi1, hi2, hi3, lo0, lo1, lo2, lo3;
        hi0 = splitpair(v0.x, v0.y, lo0);
        hi1 = splitpair(v0.z, v0.w, lo1);
        hi2 = splitpair(v1.x, v1.y, lo2);
        hi3 = splitpair(v1.z, v1.w, lo3);
        *(uint4*)&g_ihi[set][w0] = make_uint4(hi0, hi1, hi2, hi3);
        *(uint4*)&g_ilo[set][w0] = make_uint4(lo0, lo1, lo2, lo3);
    } else if (b < 4352) {
        const unsigned w = ((unsigned)(b - 4096) * 256 + tid) * 2;
        unsigned hi[2], lo[2];
        #pragma unroll
        for (int i = 0; i < 2; i++) {
            unsigned ww = w + i;
            int k2 = ww >> 9;
            int n  = ww & 511;
            float x0 = Wfe[(size_t)(2 * k2) * DF + n];
            float x1 = Wfe[(size_t)(2 * k2 + 1) * DF + n];
            hi[i] = splitpair(x0, x1, lo[i]);
        }
        *(uint2*)&g_wphi[w] = make_uint2(hi[0], hi[1]);
        *(uint2*)&g_wplo[w] = make_uint2(lo[0], lo[1]);
    } else if (b < 4964) {
        const unsigned idx = ((unsigned)(b - 4352) * 256 + tid) * 4;
        const int k2 = idx / LV_NPAD;
        const int n0 = idx % LV_NPAD;
        const int k = 2 * k2;
        unsigned hi[4], lo[4];
        #pragma unroll
        for (int i = 0; i < 4; i++) {
            int n = n0 + i;
            float x0 = (k     < T && n < T) ? Wlv[(size_t)k * T + n]       : 0.f;
            float x1 = (k + 1 < T && n < T) ? Wlv[(size_t)(k + 1) * T + n] : 0.f;
            hi[i] = splitpair(x0, x1, lo[i]);
        }
        *(uint4*)&g_wlvh[idx] = make_uint4(hi[0], hi[1], hi[2], hi[3]);
        *(uint4*)&g_wlvl[idx] = make_uint4(lo[0], lo[1], lo[2], lo[3]);
    } else {
        const int w = (b - 4964) * 8 + (tid >> 5);
        const int lane = tid & 31;
        const int set = w >> 8, e = w & 255;
        const float* tg = (set ? tetg : trtg) + (size_t)e * NS;
        float x = tg[lane];
        float s = x;
        #pragma unroll
        for (int off = 16; off > 0; off >>= 1) s += __shfl_xor_sync(0xffffffffu, s, off);
        float m = s * (1.f / NS);
        float d = x - m;
        float q = d * d;
        #pragma unroll
        for (int off = 16; off > 0; off >>= 1) q += __shfl_xor_sync(0xffffffffu, q, off);
        if (lane == 0) {
            float sd = sqrtf(q * (1.f / (NS - 1)));
            g_mu[set][e][0]  = m;
            g_mu[set][e][TT] = sd;
            unsigned short* zh = (unsigned short*)g_zhi;
            unsigned short* zl = (unsigned short*)g_zlo;
            const unsigned base = (unsigned)(set * 256 + e) * (2 * LV_KP);
            unsigned short h0, l0, h1, l1;
            split1(m,  h0, l0);
            split1(sd, h1, l1);
            zh[base + 0]  = h0;  zl[base + 0]  = l0;
            zh[base + TT] = h1;  zl[base + TT] = l1;
        }
    }
}

// ============================================================
// mma helper
// ============================================================
__device__ __forceinline__ void mma16816(float* d, const unsigned* a, const unsigned* b)
{
    asm volatile(
        "mma.sync.aligned.m16n8k16.row.col.f32.bf16.bf16.f32 "
        "{%0,%1,%2,%3}, {%4,%5,%6,%7}, {%8,%9}, {%0,%1,%2,%3};\n"
        : "+f"(d[0]), "+f"(d[1]), "+f"(d[2]), "+f"(d[3])
        : "r"(a[0]), "r"(a[1]), "r"(a[2]), "r"(a[3]), "r"(b[0]), "r"(b[1]));
}

#define AS_STRIDE 36   // uint32 words per 32-word-wide smem row (+4 pad)
#define BS_STRIDE 132  // uint32 words per 128-wide B k2-row / floats per C row

// per-lane ldmatrix address offset (bytes) within an A tile
#define LDSM_LANE_OFF(lid) ((((lid) & 15) * AS_STRIDE + ((lid) >> 4) * 4) * 4)

// ============================================================
// K1: PERSISTENT feature GEMM (HMMA). Grid = 148 CTAs, each loops over
// tiles {bid, bid+148, ...} < 512. Per tile: cp.async double-buffered
// mainloop (term-pass ordered, A via ldmatrix) + fused stats epilogue.
// Removes the 3.46-wave quantization tail of the 512-CTA launch.
// ============================================================
#define FG_BUF 70656
#define FG_TILES 512
#define FG_GRID 148

__global__ __launch_bounds__(256, 1)
void k_fgemm(const float* __restrict__ bfe)
{
    extern __shared__ unsigned char smem[];
    const int tid = threadIdx.x;
    const int wid = tid >> 5;
    const int lid = tid & 31;
    const int wm  = wid >> 2;
    const int wn  = wid & 3;
    const int gid = lid >> 2;
    const int tig = lid & 3;
    const unsigned laneoff = LDSM_LANE_OFF(lid);

    for (int tile = blockIdx.x; tile < FG_TILES; tile += FG_GRID) {
        const int ct  = tile & 3;
        const int eg  = (tile >> 2) & 63;
        const int set = tile >> 8;
        const unsigned* gih = g_ihi[set];
        const unsigned* gil = g_ilo[set];

        float acc[4][4][4];
        #pragma unroll
        for (int mt = 0; mt < 4; mt++)
            #pragma unroll
            for (int nt = 0; nt < 4; nt++)
                #pragma unroll
                for (int r = 0; r < 4; r++) acc[mt][nt][r] = 0.f;

        auto stage = [&](int c, int buf) {
            unsigned* Aw0 = (unsigned*)(smem + buf * FG_BUF);
            unsigned* Aw1 = (unsigned*)(smem + buf * FG_BUF + 18432);
            unsigned* Bw0 = (unsigned*)(smem + buf * FG_BUF + 36864);
            unsigned* Bw1 = (unsigned*)(smem + buf * FG_BUF + 53760);
            #pragma unroll
            for (int i = 0; i < 4; i++) {
                int u = tid + i * 256;
                int row = u >> 3, kp = (u & 7) * 4;
                unsigned srci = (unsigned)(eg * 128 + row) * 256 + c * 32 + kp;
                cp16(s2u(&Aw0[row * AS_STRIDE + kp]), &gih[srci]);
                cp16(s2u(&Aw1[row * AS_STRIDE + kp]), &gil[srci]);
            }
            #pragma unroll
            for (int i = 0; i < 4; i++) {
                int u = tid + i * 256;
                int k2 = u >> 5, nl = (u & 31) * 4;
                unsigned srci = (unsigned)(c * 32 + k2) * 512 + ct * 128 + nl;
                cp16(s2u(&Bw0[k2 * BS_STRIDE + nl]), &g_wphi[srci]);
                cp16(s2u(&Bw1[k2 * BS_STRIDE + nl]), &g_wplo[srci]);
            }
            asm volatile("cp.async.commit_group;\n" ::: "memory");
        };

        stage(0, 0);

        for (int chunk = 0; chunk < 8; chunk++) {
            if (chunk < 7) {
                stage(chunk + 1, (chunk + 1) & 1);
                asm volatile("cp.async.wait_group 1;\n" ::: "memory");
            } else {
                asm volatile("cp.async.wait_group 0;\n" ::: "memory");
            }
            __syncthreads();

            const int buf = chunk & 1;
            const unsigned sA0 = s2u(smem + buf * FG_BUF) + laneoff;
            const unsigned sA1 = sA0 + 18432;
            unsigned* Bw0 = (unsigned*)(smem + buf * FG_BUF + 36864);
            unsigned* Bw1 = (unsigned*)(smem + buf * FG_BUF + 53760);

            #pragma unroll
            for (int ks = 0; ks < 4; ks++) {
                const int cw = ks * 8 + tig;
                unsigned b[4][2][2];
                #pragma unroll
                for (int nt = 0; nt < 4; nt++) {
                    int n = wn * 32 + nt * 8 + gid;
                    b[nt][0][0] = Bw0[cw * BS_STRIDE + n];
                    b[nt][0][1] = Bw0[(cw + 4) * BS_STRIDE + n];
                    b[nt][1][0] = Bw1[cw * BS_STRIDE + n];
                    b[nt][1][1] = Bw1[(cw + 4) * BS_STRIDE + n];
                }
                unsigned a[4][2][4];
                #pragma unroll
                for (int mt = 0; mt < 4; mt++) {
                    unsigned aoff = (((wm * 64 + mt * 16) * AS_STRIDE) + ks * 8) * 4;
                    ldsm4(a[mt][0], sA0 + aoff);
                    ldsm4(a[mt][1], sA1 + aoff);
                }
                #pragma unroll
                for (int mt = 0; mt < 4; mt++)
                    #pragma unroll
                    for (int nt = 0; nt < 4; nt++)
                        mma16816(acc[mt][nt], a[mt][0], b[nt][0]);
                #pragma unroll
                for (int mt = 0; mt < 4; mt++)
                    #pragma unroll
                    for (int nt = 0; nt < 4; nt++)
                        mma16816(acc[mt][nt], a[mt][0], b[nt][1]);
                #pragma unroll
                for (int mt = 0; mt < 4; mt++)
                    #pragma unroll
                    for (int nt = 0; nt < 4; nt++)
                        mma16816(acc[mt][nt], a[mt][1], b[nt][0]);
            }
            __syncthreads();
        }

        float* Cs = (float*)smem;     // [128][132]
        #pragma unroll
        for (int mt = 0; mt < 4; mt++) {
            int r0 = wm * 64 + mt * 16 + gid;
            #pragma unroll
            for (int nt = 0; nt < 4; nt++) {
                int c = wn * 32 + nt * 8 + tig * 2;
                *(float2*)&Cs[r0 * BS_STRIDE + c]       = make_float2(acc[mt][nt][0], acc[mt][nt][1]);
                *(float2*)&Cs[(r0 + 8) * BS_STRIDE + c] = make_float2(acc[mt][nt][2], acc[mt][nt][3]);
            }
        }
        __syncthreads();

        {
            const int j  = tid & 127;
            const int f  = ct * 128 + j;
            const float bias = bfe[f];
            unsigned short* zh = (unsigned short*)g_zhi;
            unsigned short* zl = (unsigned short*)g_zlo;
            #pragma unroll
            for (int half = 0; half < 2; half++) {
                const int ep = (tid >> 7) * 2 + half;   // 0..3
                float s = 0.f, ss = 0.f;
                #pragma unroll
                for (int m = 0; m < NS; m++) {
                    float v = Cs[(ep * 32 + m) * BS_STRIDE + j] + bias;
                    v = fmaxf(v, 0.f);
                    s += v;
                    ss = fmaf(v, v, ss);
                }
                float mean = s * (1.f / NS);
                float var  = (ss - s * mean) * (1.f / (NS - 1));
                float stdv = sqrtf(fmaxf(var, 0.f));
                int e = eg * 4 + ep;
                g_mu[set][e][1 + f]      = mean;
                g_mu[set][e][TT + 1 + f] = stdv;
                const unsigned base = (unsigned)(set * 256 + e) * (2 * LV_KP);
                unsigned short h0, l0, h1, l1;
                split1(mean, h0, l0);
                split1(stdv, h1, l1);
                zh[base + 1 + f]      = h0;  zl[base + 1 + f]      = l0;
                zh[base + TT + 1 + f] = h1;  zl[base + TT + 1 + f] = l1;
            }
        }
        __syncthreads();   // C smem reuse safe before next tile's staging
    }
}

// ============================================================
// K2: logvar GEMM (HMMA), term-pass ordering, A via ldmatrix.
// Block 64x64, grid (18,8) = 144 blocks, 256 threads.
// Epilogue: +b_lv, clip, pairwise FEATURES (bf16-split) + H/M partials.
// ============================================================
#define LVB_STRIDE 68
#define LV_BUF 35840

__global__ __launch_bounds__(256, 1)
void k_lvgemm(const float* __restrict__ blv)
{
    extern __shared__ unsigned char smem[];

    const int bn  = blockIdx.x;
    const int bm  = blockIdx.y;
    const int tid = threadIdx.x;
    const int wid = tid >> 5;
    const int lid = tid & 31;
    const int wm  = wid >> 2;
    const int wn  = wid & 3;
    const int gid = lid >> 2;
    const int tig = lid & 3;
    const unsigned laneoff = LDSM_LANE_OFF(lid);

    float acc[2][2][4];
    #pragma unroll
    for (int mt = 0; mt < 2; mt++)
        #pragma unroll
        for (int nt = 0; nt < 2; nt++)
            #pragma unroll
            for (int r = 0; r < 4; r++) acc[mt][nt][r] = 0.f;

    auto stage = [&](int c, int buf) {
        unsigned* Aw0 = (unsigned*)(smem + buf * LV_BUF);
        unsigned* Aw1 = (unsigned*)(smem + buf * LV_BUF + 9216);
        unsigned* Bw0 = (unsigned*)(smem + buf * LV_BUF + 18432);
        unsigned* Bw1 = (unsigned*)(smem + buf * LV_BUF + 27136);
        #pragma unroll
        for (int i = 0; i < 2; i++) {
            int u = tid + i * 256;
            int row = u >> 3, kp = (u & 7) * 4;
            unsigned srci = (unsigned)(bm * 64 + row) * LV_KP + c * 32 + kp;
            cp16(s2u(&Aw0[row * AS_STRIDE + kp]), &g_zhi[srci]);
            cp16(s2u(&Aw1[row * AS_STRIDE + kp]), &g_zlo[srci]);
        }
        #pragma unroll
        for (int i = 0; i < 2; i++) {
            int u = tid + i * 256;
            int k2 = u >> 4, nl = (u & 15) * 4;
            unsigned srci = (unsigned)(c * 32 + k2) * LV_NPAD + bn * 64 + nl;
            cp16(s2u(&Bw0[k2 * LVB_STRIDE + nl]), &g_wlvh[srci]);
            cp16(s2u(&Bw1[k2 * LVB_STRIDE + nl]), &g_wlvl[srci]);
        }
        asm volatile("cp.async.commit_group;\n" ::: "memory");
    };

    stage(0, 0);

    for (int chunk = 0; chunk < 17; chunk++) {
        if (chunk < 16) {
            stage(chunk + 1, (chunk + 1) & 1);
            asm volatile("cp.async.wait_group 1;\n" ::: "memory");
        } else {
            asm volatile("cp.async.wait_group 0;\n" ::: "memory");
        }
        __syncthreads();

        const int buf = chunk & 1;
        const unsigned sA0 = s2u(smem + buf * LV_BUF) + laneoff;
        const unsigned sA1 = sA0 + 9216;
        unsigned* Bw0 = (unsigned*)(smem + buf * LV_BUF + 18432);
        unsigned* Bw1 = (unsigned*)(smem + buf * LV_BUF + 27136);

        #pragma unroll
        for (int ks = 0; ks < 4; ks++) {
            const int cw = ks * 8 + tig;
            unsigned b[2][2][2];
            #pragma unroll
            for (int nt = 0; nt < 2; nt++) {
                int n = wn * 16 + nt * 8 + gid;
                b[nt][0][0] = Bw0[cw * LVB_STRIDE + n];
                b[nt][0][1] = Bw0[(cw + 4) * LVB_STRIDE + n];
                b[nt][1][0] = Bw1[cw * LVB_STRIDE + n];
                b[nt][1][1] = Bw1[(cw + 4) * LVB_STRIDE + n];
            }
            unsigned a[2][2][4];
            #pragma unroll
            for (int mt = 0; mt < 2; mt++) {
                unsigned aoff = (((wm * 32 + mt * 16) * AS_STRIDE) + ks * 8) * 4;
                ldsm4(a[mt][0], sA0 + aoff);
                ldsm4(a[mt][1], sA1 + aoff);
            }
            #pragma unroll
            for (int mt = 0; mt < 2; mt++)
                #pragma unroll
                for (int nt = 0; nt < 2; nt++)
                    mma16816(acc[mt][nt], a[mt][0], b[nt][0]);
            #pragma unroll
            for (int mt = 0; mt < 2; mt++)
                #pragma unroll
                for (int nt = 0; nt < 2; nt++)
                    mma16816(acc[mt][nt], a[mt][0], b[nt][1]);
            #pragma unroll
            for (int mt = 0; mt < 2; mt++)
                #pragma unroll
                for (int nt = 0; nt < 2; nt++)
                    mma16816(acc[mt][nt], a[mt][1], b[nt][0]);
        }
        __syncthreads();
    }

    float* Cs = (float*)smem;                  // [64][68]
    float* hq = (float*)(smem + 17408);        // [64][2]
    float* mq = (float*)(smem + 17920);        // [64][2]
    #pragma unroll
    for (int mt = 0; mt < 2; mt++) {
        int r0 = wm * 32 + mt * 16 + gid;
        #pragma unroll
        for (int nt = 0; nt < 2; nt++) {
            int c = wn * 16 + nt * 8 + tig * 2;
            *(float2*)&Cs[r0 * LVB_STRIDE + c]       = make_float2(acc[mt][nt][0], acc[mt][nt][1]);
            *(float2*)&Cs[(r0 + 8) * LVB_STRIDE + c] = make_float2(acc[mt][nt][2], acc[mt][nt][3]);
        }
    }
    __syncthreads();

    {
        const int j    = tid & 63;
        const int rg   = tid >> 6;
        const int w2   = (tid >> 5) & 1;
        const int lane = tid & 31;
        const int n = bn * 64 + j;
        const bool valid = (n < T);
        const float bias = valid ? blv[n] : 0.f;
        const int set_blk = (bm >= 4);
        const int ebase = (bm & 3) * 64;

        #pragma unroll
        for (int rr = 0; rr < 16; rr++) {
            int r = rg * 16 + rr;
            float lv = fminf(fmaxf(Cs[r * LVB_STRIDE + j] + bias, -9.f), -2.f);
            float h = valid ? lv : 0.f;
            float mm = 0.f;
            if (valid) {
                int e = ebase + r;
                float m   = g_mu[set_blk][e][n];
                float elv = expf(lv);
                float eml = expf(-lv);
                mm = m * m * eml;
                float f0, f1, f2, f3;
                if (set_blk == 0) {
                    f0 = elv + m * m;  f1 = eml;         f2 = m * eml;    f3 = m;
                } else {
                    f0 = eml;          f1 = elv + m * m; f2 = -2.f * m;   f3 = -2.f * m * eml;
                }
                unsigned lo0, lo1, hi0, hi1;
                hi0 = splitpair(f0, f1, lo0);
                hi1 = splitpair(f2, f3, lo1);
                unsigned widx = (unsigned)e * PK_STRIDE + 2 * n;
                if (set_blk == 0) {
                    *(uint2*)&g_pAhi[widx] = make_uint2(hi0, hi1);
                    *(uint2*)&g_pAlo[widx] = make_uint2(lo0, lo1);
                } else {
                    *(uint2*)&g_pBhi[widx] = make_uint2(hi0, hi1);
                    *(uint2*)&g_pBlo[widx] = make_uint2(lo0, lo1);
                }
            }
            #pragma unroll
            for (int off = 16; off > 0; off >>= 1) {
                h  += __shfl_down_sync(0xffffffffu, h,  off);
                mm += __shfl_down_sync(0xffffffffu, mm, off);
            }
            if (lane == 0) { hq[r * 2 + w2] = h; mq[r * 2 + w2] = mm; }
        }
    }
    __syncthreads();
    if (tid < 64) {
        g_Hpart[bn][bm * 64 + tid] = hq[tid * 2] + hq[tid * 2 + 1];
        g_Mpart[bn][bm * 64 + tid] = mq[tid * 2] + mq[tid * 2 + 1];
    }
}

// ============================================================
// K3: pairwise GEMM (HMMA), term-pass ordering, A via ldmatrix.
// spart[z][i][j] over chunks {z, z+9, ...} < 65. grid (4,4,9) = 144.
// ============================================================
#define PG_BUF 36864

__global__ __launch_bounds__(256, 1)
void k_pgemm()
{
    extern __shared__ unsigned char smem[];
    const int j0  = blockIdx.x * 64;
    const int i0  = blockIdx.y * 64;
    const int bz  = blockIdx.z;
    const int tid = threadIdx.x;
    const int wid = tid >> 5;
    const int lid = tid & 31;
    const int wm  = wid >> 2;
    const int wn  = wid & 3;
    const int gid = lid >> 2;
    const int tig = lid & 3;
    const unsigned laneoff = LDSM_LANE_OFF(lid);

    float acc[2][2][4];
    #pragma unroll
    for (int mt = 0; mt < 2; mt++)
        #pragma unroll
        for (int nt = 0; nt < 2; nt++)
            #pragma unroll
            for (int r = 0; r < 4; r++) acc[mt][nt][r] = 0.f;

    auto stage = [&](int c, int buf) {
        unsigned* Ah = (unsigned*)(smem + buf * PG_BUF);
        unsigned* Al = (unsigned*)(smem + buf * PG_BUF + 9216);
        unsigned* Bh = (unsigned*)(smem + buf * PG_BUF + 18432);
        unsigned* Bl = (unsigned*)(smem + buf * PG_BUF + 27648);
        #pragma unroll
        for (int i = 0; i < 2; i++) {
            int u = tid + i * 256;
            int row = u >> 3, kp = (u & 7) * 4;
            unsigned sa = (unsigned)(i0 + row) * PK_STRIDE + c * 32 + kp;
            unsigned sb = (unsigned)(j0 + row) * PK_STRIDE + c * 32 + kp;
            cp16(s2u(&Ah[row * AS_STRIDE + kp]), &g_pAhi[sa]);
            cp16(s2u(&Al[row * AS_STRIDE + kp]), &g_pAlo[sa]);
            cp16(s2u(&Bh[row * AS_STRIDE + kp]), &g_pBhi[sb]);
            cp16(s2u(&Bl[row * AS_STRIDE + kp]), &g_pBlo[sb]);
        }
        asm volatile("cp.async.commit_group;\n" ::: "memory");
    };

    stage(bz, 0);

    int buf = 0;
    for (int c = bz; c < PK_CHUNKS; c += PK_SLICES, buf ^= 1) {
        int nc = c + PK_SLICES;
        if (nc < PK_CHUNKS) {
            stage(nc, buf ^ 1);
            asm volatile("cp.async.wait_group 1;\n" ::: "memory");
        } else {
            asm volatile("cp.async.wait_group 0;\n" ::: "memory");
        }
        __syncthreads();

        const unsigned sA0 = s2u(smem + buf * PG_BUF) + laneoff;
        const unsigned sA1 = sA0 + 9216;
        unsigned* Bh = (unsigned*)(smem + buf * PG_BUF + 18432);
        unsigned* Bl = (unsigned*)(smem + buf * PG_BUF + 27648);

        #pragma unroll
        for (int ks = 0; ks < 4; ks++) {
            const int cw = ks * 8 + tig;
            unsigned b[2][2][2];
            #pragma unroll
            for (int nt = 0; nt < 2; nt++) {
                int n = wn * 16 + nt * 8 + gid;
                b[nt][0][0] = Bh[n * AS_STRIDE + cw];
                b[nt][0][1] = Bh[n * AS_STRIDE + cw + 4];
                b[nt][1][0] = Bl[n * AS_STRIDE + cw];
                b[nt][1][1] = Bl[n * AS_STRIDE + cw + 4];
            }
            unsigned a[2][2][4];
            #pragma unroll
            for (int mt = 0; mt < 2; mt++) {
                unsigned aoff = (((wm * 32 + mt * 16) * AS_STRIDE) + ks * 8) * 4;
                ldsm4(a[mt][0], sA0 + aoff);
                ldsm4(a[mt][1], sA1 + aoff);
            }
            #pragma unroll
            for (int mt = 0; mt < 2; mt++)
                #pragma unroll
                for (int nt = 0; nt < 2; nt++)
                    mma16816(acc[mt][nt], a[mt][0], b[nt][0]);
            #pragma unroll
            for (int mt = 0; mt < 2; mt++)
                #pragma unroll
                for (int nt = 0; nt < 2; nt++)
                    mma16816(acc[mt][nt], a[mt][0], b[nt][1]);
            #pragma unroll
            for (int mt = 0; mt < 2; mt++)
                #pragma unroll
                for (int nt = 0; nt < 2; nt++)
                    mma16816(acc[mt][nt], a[mt][1], b[nt][0]);
        }
        __syncthreads();
    }

    #pragma unroll
    for (int mt = 0; mt < 2; mt++) {
        int r0 = i0 + wm * 32 + mt * 16 + gid;
        #pragma unroll
        for (int nt = 0; nt < 2; nt++) {
            int c = j0 + wn * 16 + nt * 8 + tig * 2;
            *(float2*)&g_spart[bz][r0][c]     = make_float2(acc[mt][nt][0], acc[mt][nt][1]);
            *(float2*)&g_spart[bz][r0 + 8][c] = make_float2(acc[mt][nt][2], acc[mt][nt][3]);
        }
    }
}

// ============================================================
// K4: assemble score + log_softmax + classes tail.
// ============================================================
__global__ void k_softmax(float* __restrict__ out, int out_size)
{
    const int i = blockIdx.x;
    const int j = threadIdx.x;
    __shared__ float red[256];

    float s = 0.f;
    #pragma unroll
    for (int z = 0; z < PK_SLICES; z++) s += g_spart[z][i][j];

    float H0 = 0.5f * (float)T * LOG_2PIE;
    float H1 = H0;
    float M0 = 0.f, M1 = 0.f;
    #pragma unroll
    for (int b = 0; b < 18; b++) {
        H0 += g_Hpart[b][i];
        H1 += g_Hpart[b][NEP + j];
        M0 += g_Mpart[b][i];
        M1 += g_Mpart[b][NEP + j];
    }
    float score = 0.5f * (s + M0 + M1) - (float)T + H0 + H1;
    float v = -score;

    red[j] = v;
    __syncthreads();
    for (int st = 128; st > 0; st >>= 1) {
        if (j < st) red[j] = fmaxf(red[j], red[j + st]);
        __syncthreads();
    }
    float mx = red[0];
    __syncthreads();
    float ex = expf(v - mx);
    red[j] = ex;
    __syncthreads();
    for (int st = 128; st > 0; st >>= 1) {
        if (j < st) red[j] += red[j + st];
        __syncthreads();
    }
    float lse = mx + logf(red[0]);
    out[(size_t)i * NEP + j] = v - lse;

    if (j == 0 && NEP * NEP + i < out_size)
        out[NEP * NEP + i] = (float)i;
}

// ============================================================
extern "C" void kernel_launch(void* const* d_in, const int* in_sizes, int n_in,
                              void* d_out, int out_size)
{
    const float* train_inputs  = (const float*)d_in[0];
    const float* train_targets = (const float*)d_in[1];
    const float* test_inputs   = (const float*)d_in[2];
    const float* test_targets  = (const float*)d_in[3];
    const float* W_fe          = (const float*)d_in[4];
    const float* b_fe          = (const float*)d_in[5];
    const float* W_lv          = (const float*)d_in[6];
    const float* b_lv          = (const float*)d_in[7];
    float* out = (float*)d_out;

    const int smem_fgemm = 2 * FG_BUF;           // 141312
    const int smem_lv    = 2 * LV_BUF;           // 71680
    const int smem_pg    = 2 * PG_BUF;           // 73728
    cudaFuncSetAttribute(k_fgemm,  cudaFuncAttributeMaxDynamicSharedMemorySize, smem_fgemm);
    cudaFuncSetAttribute(k_lvgemm, cudaFuncAttributeMaxDynamicSharedMemorySize, smem_lv);
    cudaFuncSetAttribute(k_pgemm,  cudaFuncAttributeMaxDynamicSharedMemorySize, smem_pg);

    k_prep<<<5028, 256>>>(train_inputs, test_inputs, W_fe, W_lv,
                          train_targets, test_targets);
    k_fgemm<<<FG_GRID, 256, smem_fgemm>>>(b_fe);
    k_lvgemm<<<dim3(18, 8), 256, smem_lv>>>(b_lv);
    k_pgemm<<<dim3(4, 4, PK_SLICES), 256, smem_pg>>>();
    k_softmax<<<NEP, 256>>>(out, out_size);
}

// round 16
// speedup vs baseline: 1.0638x; 1.0638x over previous
#include <cuda_runtime.h>
#include <cuda_bf16.h>
#include <math.h>

#define NEP 256
#define NS  32
#define DIN 512
#define DF  512
#define T   1026
#define TT  513

#define LOG_2PIE 2.8378770664093453f

// K geometry for the logvar GEMM: K=1026 -> 513 k-pairs -> pad to 544 (17 chunks of 32)
#define LV_KP   544
#define LV_NPAD 1152   // 18 tiles of 64

// pair-GEMM K geometry: K = 4*1026 = 4104 -> 2052 pairs -> pad to 2080 (65 chunks of 32)
#define PK_STRIDE 2080
#define PK_CHUNKS 65
#define PK_SLICES 9

// -------- device scratch (no allocations allowed) --------
__device__ float g_mu [2][NEP][T];   // z (mu)
__device__ float g_Hpart[18][512];   // per-Ntile partial sums of lv per row (row = set*256+e)
__device__ float g_Mpart[18][512];   // per-Ntile partial sums of m^2*exp(-lv) per row
__device__ float g_spart[PK_SLICES][NEP][NEP]; // pairwise score partials per K-slice

// bf16 split operands. Inputs: [set][8192 rows][256 k-pair words] (K contiguous)
__device__ __align__(16) unsigned g_ihi[2][8192 * 256];
__device__ __align__(16) unsigned g_ilo[2][8192 * 256];
// W_fe split, k-pair interleaved: word (k2, n) holds halves (k=2*k2, 2*k2+1) of column n
__device__ __align__(16) unsigned g_wphi[256 * 512];
__device__ __align__(16) unsigned g_wplo[256 * 512];
// z split: [512 rows (set*256+e)][544 k-pair words]; pad never written (zero-init)
__device__ __align__(16) unsigned g_zhi[512 * LV_KP];
__device__ __align__(16) unsigned g_zlo[512 * LV_KP];
// W_lv split (padded)
__device__ __align__(16) unsigned g_wlvh[LV_KP * LV_NPAD];
__device__ __align__(16) unsigned g_wlvl[LV_KP * LV_NPAD];
// pairwise feature rows, bf16 split, k = 4*n + f (f=0..3), pad zero-init
__device__ __align__(16) unsigned g_pAhi[NEP * PK_STRIDE];
__device__ __align__(16) unsigned g_pAlo[NEP * PK_STRIDE];
__device__ __align__(16) unsigned g_pBhi[NEP * PK_STRIDE];
__device__ __align__(16) unsigned g_pBlo[NEP * PK_STRIDE];

// ============================================================
__device__ __forceinline__ void split1(float x, unsigned short& h, unsigned short& l)
{
    __nv_bfloat16 bh = __float2bfloat16(x);
    float r = x - __bfloat162float(bh);
    __nv_bfloat16 bl = __float2bfloat16(r);
    h = __bfloat16_as_ushort(bh);
    l = __bfloat16_as_ushort(bl);
}

__device__ __forceinline__ unsigned splitpair(float x0, float x1, unsigned& lo)
{
    unsigned short h0, l0, h1, l1;
    split1(x0, h0, l0);
    split1(x1, h1, l1);
    lo = (unsigned)l0 | ((unsigned)l1 << 16);
    return (unsigned)h0 | ((unsigned)h1 << 16);
}

__device__ __forceinline__ void cp16(unsigned saddr, const void* g)
{
    asm volatile("cp.async.cg.shared.global [%0], [%1], 16;\n" :: "r"(saddr), "l"(g));
}
__device__ __forceinline__ unsigned s2u(const void* p)
{
    return (unsigned)__cvta_generic_to_shared(p);
}
__device__ __forceinline__ void ldsm4(unsigned* r, unsigned addr)
{
    asm volatile("ldmatrix.sync.aligned.m8n8.x4.shared.b16 {%0,%1,%2,%3}, [%4];"
                 : "=r"(r[0]), "=r"(r[1]), "=r"(r[2]), "=r"(r[3]) : "r"(addr));
}

// ============================================================
// merged prep, 4x-vectorized (round-11 proven config)
// ============================================================
__global__ void k_prep(const float* __restrict__ trin, const float* __restrict__ tein,
                       const float* __restrict__ Wfe, const float* __restrict__ Wlv,
                       const float* __restrict__ trtg, const float* __restrict__ tetg)
{
    const int b = blockIdx.x;
    const int tid = threadIdx.x;

    if (b < 4096) {
        const int set = b >> 11;
        const unsigned w0 = ((unsigned)(b & 2047) * 256 + tid) * 4;
        const float4* src = (const float4*)(set ? tein : trin);
        float4 v0 = src[w0 >> 1];
        float4 v1 = src[(w0 >> 1) + 1];
        unsigned hi0, hi1, hi2, hi3, lo0, lo1, lo2, lo3;
        hi0 = splitpair(v0.x, v0.y, lo0);
        hi1 = splitpair(v0.z, v0.w, lo1);
        hi2 = splitpair(v1.x, v1.y, lo2);
        hi3 = splitpair(v1.z, v1.w, lo3);
        *(uint4*)&g_ihi[set][w0] = make_uint4(hi0, hi1, hi2, hi3);
        *(uint4*)&g_ilo[set][w0] = make_uint4(lo0, lo1, lo2, lo3);
    } else if (b < 4352) {
        const unsigned w = ((unsigned)(b - 4096) * 256 + tid) * 2;
        unsigned hi[2], lo[2];
        #pragma unroll
        for (int i = 0; i < 2; i++) {
            unsigned ww = w + i;
            int k2 = ww >> 9;
            int n  = ww & 511;
            float x0 = Wfe[(size_t)(2 * k2) * DF + n];
            float x1 = Wfe[(size_t)(2 * k2 + 1) * DF + n];
            hi[i] = splitpair(x0, x1, lo[i]);
        }
        *(uint2*)&g_wphi[w] = make_uint2(hi[0], hi[1]);
        *(uint2*)&g_wplo[w] = make_uint2(lo[0], lo[1]);
    } else if (b < 4964) {
        const unsigned idx = ((unsigned)(b - 4352) * 256 + tid) * 4;
        const int k2 = idx / LV_NPAD;
        const int n0 = idx % LV_NPAD;
        const int k = 2 * k2;
        unsigned hi[4], lo[4];
        #pragma unroll
        for (int i = 0; i < 4; i++) {
            int n = n0 + i;
            float x0 = (k     < T && n < T) ? Wlv[(size_t)k * T + n]       : 0.f;
            float x1 = (k + 1 < T && n < T) ? Wlv[(size_t)(k + 1) * T + n] : 0.f;
            hi[i] = splitpair(x0, x1, lo[i]);
        }
        *(uint4*)&g_wlvh[idx] = make_uint4(hi[0], hi[1], hi[2], hi[3]);
        *(uint4*)&g_wlvl[idx] = make_uint4(lo[0], lo[1], lo[2], lo[3]);
    } else {
        const int w = (b - 4964) * 8 + (tid >> 5);
        const int lane = tid & 31;
        const int set = w >> 8, e = w & 255;
        const float* tg = (set ? tetg : trtg) + (size_t)e * NS;
        float x = tg[lane];
        float s = x;
        #pragma unroll
        for (int off = 16; off > 0; off >>= 1) s += __shfl_xor_sync(0xffffffffu, s, off);
        float m = s * (1.f / NS);
        float d = x - m;
        float q = d * d;
        #pragma unroll
        for (int off = 16; off > 0; off >>= 1) q += __shfl_xor_sync(0xffffffffu, q, off);
        if (lane == 0) {
            float sd = sqrtf(q * (1.f / (NS - 1)));
            g_mu[set][e][0]  = m;
            g_mu[set][e][TT] = sd;
            unsigned short* zh = (unsigned short*)g_zhi;
            unsigned short* zl = (unsigned short*)g_zlo;
            const unsigned base = (unsigned)(set * 256 + e) * (2 * LV_KP);
            unsigned short h0, l0, h1, l1;
            split1(m,  h0, l0);
            split1(sd, h1, l1);
            zh[base + 0]  = h0;  zl[base + 0]  = l0;
            zh[base + TT] = h1;  zl[base + TT] = l1;
        }
    }
}

// ============================================================
// mma helper
// ============================================================
__device__ __forceinline__ void mma16816(float* d, const unsigned* a, const unsigned* b)
{
    asm volatile(
        "mma.sync.aligned.m16n8k16.row.col.f32.bf16.bf16.f32 "
        "{%0,%1,%2,%3}, {%4,%5,%6,%7}, {%8,%9}, {%0,%1,%2,%3};\n"
        : "+f"(d[0]), "+f"(d[1]), "+f"(d[2]), "+f"(d[3])
        : "r"(a[0]), "r"(a[1]), "r"(a[2]), "r"(a[3]), "r"(b[0]), "r"(b[1]));
}

#define AS_STRIDE 36   // uint32 words per 32-word-wide smem row (+4 pad)
#define FB_STRIDE 136  // fgemm B row stride: bank step 8*tig+gid -> conflict-free

// per-lane ldmatrix address offset (bytes) within an A tile
#define LDSM_LANE_OFF(lid) ((((lid) & 15) * AS_STRIDE + ((lid) >> 4) * 4) * 4)

// ============================================================
// K1: PERSISTENT feature GEMM (HMMA). Grid = 148 CTAs over 512 tiles.
// B smem stride 136 -> conflict-free B fragment reads (the crossbar fix).
// cp.async double-buffered, A via ldmatrix, term-pass ordered.
// Fused bias/relu/mean/std epilogue + z-split.
// ============================================================
#define FG_BUF 71680   // A 2*18432 + B 2*17408
#define FG_TILES 512
#define FG_GRID 148

__global__ __launch_bounds__(256, 1)
void k_fgemm(const float* __restrict__ bfe)
{
    extern __shared__ unsigned char smem[];
    const int tid = threadIdx.x;
    const int wid = tid >> 5;
    const int lid = tid & 31;
    const int wm  = wid >> 2;
    const int wn  = wid & 3;
    const int gid = lid >> 2;
    const int tig = lid & 3;
    const unsigned laneoff = LDSM_LANE_OFF(lid);

    for (int tile = blockIdx.x; tile < FG_TILES; tile += FG_GRID) {
        const int ct  = tile & 3;
        const int eg  = (tile >> 2) & 63;
        const int set = tile >> 8;
        const unsigned* gih = g_ihi[set];
        const unsigned* gil = g_ilo[set];

        float acc[4][4][4];
        #pragma unroll
        for (int mt = 0; mt < 4; mt++)
            #pragma unroll
            for (int nt = 0; nt < 4; nt++)
                #pragma unroll
                for (int r = 0; r < 4; r++) acc[mt][nt][r] = 0.f;

        auto stage = [&](int c, int buf) {
            unsigned* Aw0 = (unsigned*)(smem + buf * FG_BUF);
            unsigned* Aw1 = (unsigned*)(smem + buf * FG_BUF + 18432);
            unsigned* Bw0 = (unsigned*)(smem + buf * FG_BUF + 36864);
            unsigned* Bw1 = (unsigned*)(smem + buf * FG_BUF + 54272);
            #pragma unroll
            for (int i = 0; i < 4; i++) {
                int u = tid + i * 256;
                int row = u >> 3, kp = (u & 7) * 4;
                unsigned srci = (unsigned)(eg * 128 + row) * 256 + c * 32 + kp;
                cp16(s2u(&Aw0[row * AS_STRIDE + kp]), &gih[srci]);
                cp16(s2u(&Aw1[row * AS_STRIDE + kp]), &gil[srci]);
            }
            #pragma unroll
            for (int i = 0; i < 4; i++) {
                int u = tid + i * 256;
                int k2 = u >> 5, nl = (u & 31) * 4;
                unsigned srci = (unsigned)(c * 32 + k2) * 512 + ct * 128 + nl;
                cp16(s2u(&Bw0[k2 * FB_STRIDE + nl]), &g_wphi[srci]);
                cp16(s2u(&Bw1[k2 * FB_STRIDE + nl]), &g_wplo[srci]);
            }
            asm volatile("cp.async.commit_group;\n" ::: "memory");
        };

        stage(0, 0);

        for (int chunk = 0; chunk < 8; chunk++) {
            if (chunk < 7) {
                stage(chunk + 1, (chunk + 1) & 1);
                asm volatile("cp.async.wait_group 1;\n" ::: "memory");
            } else {
                asm volatile("cp.async.wait_group 0;\n" ::: "memory");
            }
            __syncthreads();

            const int buf = chunk & 1;
            const unsigned sA0 = s2u(smem + buf * FG_BUF) + laneoff;
            const unsigned sA1 = sA0 + 18432;
            unsigned* Bw0 = (unsigned*)(smem + buf * FG_BUF + 36864);
            unsigned* Bw1 = (unsigned*)(smem + buf * FG_BUF + 54272);

            #pragma unroll
            for (int ks = 0; ks < 4; ks++) {
                const int cw = ks * 8 + tig;
                unsigned b[4][2][2];
                #pragma unroll
                for (int nt = 0; nt < 4; nt++) {
                    int n = wn * 32 + nt * 8 + gid;
                    b[nt][0][0] = Bw0[cw * FB_STRIDE + n];
                    b[nt][0][1] = Bw0[(cw + 4) * FB_STRIDE + n];
                    b[nt][1][0] = Bw1[cw * FB_STRIDE + n];
                    b[nt][1][1] = Bw1[(cw + 4) * FB_STRIDE + n];
                }
                unsigned a[4][2][4];
                #pragma unroll
                for (int mt = 0; mt < 4; mt++) {
                    unsigned aoff = (((wm * 64 + mt * 16) * AS_STRIDE) + ks * 8) * 4;
                    ldsm4(a[mt][0], sA0 + aoff);
                    ldsm4(a[mt][1], sA1 + aoff);
                }
                #pragma unroll
                for (int mt = 0; mt < 4; mt++)
                    #pragma unroll
                    for (int nt = 0; nt < 4; nt++)
                        mma16816(acc[mt][nt], a[mt][0], b[nt][0]);
                #pragma unroll
                for (int mt = 0; mt < 4; mt++)
                    #pragma unroll
                    for (int nt = 0; nt < 4; nt++)
                        mma16816(acc[mt][nt], a[mt][0], b[nt][1]);
                #pragma unroll
                for (int mt = 0; mt < 4; mt++)
                    #pragma unroll
                    for (int nt = 0; nt < 4; nt++)
                        mma16816(acc[mt][nt], a[mt][1], b[nt][0]);
            }
            __syncthreads();
        }

        float* Cs = (float*)smem;     // [128][136]
        #pragma unroll
        for (int mt = 0; mt < 4; mt++) {
            int r0 = wm * 64 + mt * 16 + gid;
            #pragma unroll
            for (int nt = 0; nt < 4; nt++) {
                int c = wn * 32 + nt * 8 + tig * 2;
                *(float2*)&Cs[r0 * FB_STRIDE + c]       = make_float2(acc[mt][nt][0], acc[mt][nt][1]);
                *(float2*)&Cs[(r0 + 8) * FB_STRIDE + c] = make_float2(acc[mt][nt][2], acc[mt][nt][3]);
            }
        }
        __syncthreads();

        {
            const int j  = tid & 127;
            const int f  = ct * 128 + j;
            const float bias = bfe[f];
            unsigned short* zh = (unsigned short*)g_zhi;
            unsigned short* zl = (unsigned short*)g_zlo;
            #pragma unroll
            for (int half = 0; half < 2; half++) {
                const int ep = (tid >> 7) * 2 + half;   // 0..3
                float s = 0.f, ss = 0.f;
                #pragma unroll
                for (int m = 0; m < NS; m++) {
                    float v = Cs[(ep * 32 + m) * FB_STRIDE + j] + bias;
                    v = fmaxf(v, 0.f);
                    s += v;
                    ss = fmaf(v, v, ss);
                }
                float mean = s * (1.f / NS);
                float var  = (ss - s * mean) * (1.f / (NS - 1));
                float stdv = sqrtf(fmaxf(var, 0.f));
                int e = eg * 4 + ep;
                g_mu[set][e][1 + f]      = mean;
                g_mu[set][e][TT + 1 + f] = stdv;
                const unsigned base = (unsigned)(set * 256 + e) * (2 * LV_KP);
                unsigned short h0, l0, h1, l1;
                split1(mean, h0, l0);
                split1(stdv, h1, l1);
                zh[base + 1 + f]      = h0;  zl[base + 1 + f]      = l0;
                zh[base + TT + 1 + f] = h1;  zl[base + TT + 1 + f] = l1;
            }
        }
        __syncthreads();
    }
}

// ============================================================
// K2: logvar GEMM (HMMA), B stride 72 (conflict-free), term-pass ordered.
// Block 64x64, grid (18,8) = 144 blocks, 256 threads.
// Epilogue: +b_lv, clip, pairwise FEATURES (bf16-split) + H/M partials.
// ============================================================
#define LVB_STRIDE 72
#define LV_BUF 36864   // A 2*9216 + B 2*9216

__global__ __launch_bounds__(256, 1)
void k_lvgemm(const float* __restrict__ blv)
{
    extern __shared__ unsigned char smem[];

    const int bn  = blockIdx.x;
    const int bm  = blockIdx.y;
    const int tid = threadIdx.x;
    const int wid = tid >> 5;
    const int lid = tid & 31;
    const int wm  = wid >> 2;
    const int wn  = wid & 3;
    const int gid = lid >> 2;
    const int tig = lid & 3;
    const unsigned laneoff = LDSM_LANE_OFF(lid);

    float acc[2][2][4];
    #pragma unroll
    for (int mt = 0; mt < 2; mt++)
        #pragma unroll
        for (int nt = 0; nt < 2; nt++)
            #pragma unroll
            for (int r = 0; r < 4; r++) acc[mt][nt][r] = 0.f;

    auto stage = [&](int c, int buf) {
        unsigned* Aw0 = (unsigned*)(smem + buf * LV_BUF);
        unsigned* Aw1 = (unsigned*)(smem + buf * LV_BUF + 9216);
        unsigned* Bw0 = (unsigned*)(smem + buf * LV_BUF + 18432);
        unsigned* Bw1 = (unsigned*)(smem + buf * LV_BUF + 27648);
        #pragma unroll
        for (int i = 0; i < 2; i++) {
            int u = tid + i * 256;
            int row = u >> 3, kp = (u & 7) * 4;
            unsigned srci = (unsigned)(bm * 64 + row) * LV_KP + c * 32 + kp;
            cp16(s2u(&Aw0[row * AS_STRIDE + kp]), &g_zhi[srci]);
            cp16(s2u(&Aw1[row * AS_STRIDE + kp]), &g_zlo[srci]);
        }
        #pragma unroll
        for (int i = 0; i < 2; i++) {
            int u = tid + i * 256;
            int k2 = u >> 4, nl = (u & 15) * 4;
            unsigned srci = (unsigned)(c * 32 + k2) * LV_NPAD + bn * 64 + nl;
            cp16(s2u(&Bw0[k2 * LVB_STRIDE + nl]), &g_wlvh[srci]);
            cp16(s2u(&Bw1[k2 * LVB_STRIDE + nl]), &g_wlvl[srci]);
        }
        asm volatile("cp.async.commit_group;\n" ::: "memory");
    };

    stage(0, 0);

    for (int chunk = 0; chunk < 17; chunk++) {
        if (chunk < 16) {
            stage(chunk + 1, (chunk + 1) & 1);
            asm volatile("cp.async.wait_group 1;\n" ::: "memory");
        } else {
            asm volatile("cp.async.wait_group 0;\n" ::: "memory");
        }
        __syncthreads();

        const int buf = chunk & 1;
        const unsigned sA0 = s2u(smem + buf * LV_BUF) + laneoff;
        const unsigned sA1 = sA0 + 9216;
        unsigned* Bw0 = (unsigned*)(smem + buf * LV_BUF + 18432);
        unsigned* Bw1 = (unsigned*)(smem + buf * LV_BUF + 27648);

        #pragma unroll
        for (int ks = 0; ks < 4; ks++) {
            const int cw = ks * 8 + tig;
            unsigned b[2][2][2];
            #pragma unroll
            for (int nt = 0; nt < 2; nt++) {
                int n = wn * 16 + nt * 8 + gid;
                b[nt][0][0] = Bw0[cw * LVB_STRIDE + n];
                b[nt][0][1] = Bw0[(cw + 4) * LVB_STRIDE + n];
                b[nt][1][0] = Bw1[cw * LVB_STRIDE + n];
                b[nt][1][1] = Bw1[(cw + 4) * LVB_STRIDE + n];
            }
            unsigned a[2][2][4];
            #pragma unroll
            for (int mt = 0; mt < 2; mt++) {
                unsigned aoff = (((wm * 32 + mt * 16) * AS_STRIDE) + ks * 8) * 4;
                ldsm4(a[mt][0], sA0 + aoff);
                ldsm4(a[mt][1], sA1 + aoff);
            }
            #pragma unroll
            for (int mt = 0; mt < 2; mt++)
                #pragma unroll
                for (int nt = 0; nt < 2; nt++)
                    mma16816(acc[mt][nt], a[mt][0], b[nt][0]);
            #pragma unroll
            for (int mt = 0; mt < 2; mt++)
                #pragma unroll
                for (int nt = 0; nt < 2; nt++)
                    mma16816(acc[mt][nt], a[mt][0], b[nt][1]);
            #pragma unroll
            for (int mt = 0; mt < 2; mt++)
                #pragma unroll
                for (int nt = 0; nt < 2; nt++)
                    mma16816(acc[mt][nt], a[mt][1], b[nt][0]);
        }
        __syncthreads();
    }

    float* Cs = (float*)smem;                  // [64][72]
    float* hq = (float*)(smem + 18432);        // [64][2]
    float* mq = (float*)(smem + 18944);        // [64][2]
    #pragma unroll
    for (int mt = 0; mt < 2; mt++) {
        int r0 = wm * 32 + mt * 16 + gid;
        #pragma unroll
        for (int nt = 0; nt < 2; nt++) {
            int c = wn * 16 + nt * 8 + tig * 2;
            *(float2*)&Cs[r0 * LVB_STRIDE + c]       = make_float2(acc[mt][nt][0], acc[mt][nt][1]);
            *(float2*)&Cs[(r0 + 8) * LVB_STRIDE + c] = make_float2(acc[mt][nt][2], acc[mt][nt][3]);
        }
    }
    __syncthreads();

    {
        const int j    = tid & 63;
        const int rg   = tid >> 6;
        const int w2   = (tid >> 5) & 1;
        const int lane = tid & 31;
        const int n = bn * 64 + j;
        const bool valid = (n < T);
        const float bias = valid ? blv[n] : 0.f;
        const int set_blk = (bm >= 4);
        const int ebase = (bm & 3) * 64;

        #pragma unroll
        for (int rr = 0; rr < 16; rr++) {
            int r = rg * 16 + rr;
            float lv = fminf(fmaxf(Cs[r * LVB_STRIDE + j] + bias, -9.f), -2.f);
            float h = valid ? lv : 0.f;
            float mm = 0.f;
            if (valid) {
                int e = ebase + r;
                float m   = g_mu[set_blk][e][n];
                float elv = expf(lv);
                float eml = expf(-lv);
                mm = m * m * eml;
                float f0, f1, f2, f3;
                if (set_blk == 0) {
                    f0 = elv + m * m;  f1 = eml;         f2 = m * eml;    f3 = m;
                } else {
                    f0 = eml;          f1 = elv + m * m; f2 = -2.f * m;   f3 = -2.f * m * eml;
                }
                unsigned lo0, lo1, hi0, hi1;
                hi0 = splitpair(f0, f1, lo0);
                hi1 = splitpair(f2, f3, lo1);
                unsigned widx = (unsigned)e * PK_STRIDE + 2 * n;
                if (set_blk == 0) {
                    *(uint2*)&g_pAhi[widx] = make_uint2(hi0, hi1);
                    *(uint2*)&g_pAlo[widx] = make_uint2(lo0, lo1);
                } else {
                    *(uint2*)&g_pBhi[widx] = make_uint2(hi0, hi1);
                    *(uint2*)&g_pBlo[widx] = make_uint2(lo0, lo1);
                }
            }
            #pragma unroll
            for (int off = 16; off > 0; off >>= 1) {
                h  += __shfl_down_sync(0xffffffffu, h,  off);
                mm += __shfl_down_sync(0xffffffffu, mm, off);
            }
            if (lane == 0) { hq[r * 2 + w2] = h; mq[r * 2 + w2] = mm; }
        }
    }
    __syncthreads();
    if (tid < 64) {
        g_Hpart[bn][bm * 64 + tid] = hq[tid * 2] + hq[tid * 2 + 1];
        g_Mpart[bn][bm * 64 + tid] = mq[tid * 2] + mq[tid * 2 + 1];
    }
}

// ============================================================
// K3: pairwise GEMM (HMMA), term-pass ordered, A via ldmatrix.
// (B reads n-major are already conflict-free here.)
// spart[z][i][j] over chunks {z, z+9, ...} < 65. grid (4,4,9) = 144.
// ============================================================
#define PG_BUF 36864

__global__ __launch_bounds__(256, 1)
void k_pgemm()
{
    extern __shared__ unsigned char smem[];
    const int j0  = blockIdx.x * 64;
    const int i0  = blockIdx.y * 64;
    const int bz  = blockIdx.z;
    const int tid = threadIdx.x;
    const int wid = tid >> 5;
    const int lid = tid & 31;
    const int wm  = wid >> 2;
    const int wn  = wid & 3;
    const int gid = lid >> 2;
    const int tig = lid & 3;
    const unsigned laneoff = LDSM_LANE_OFF(lid);

    float acc[2][2][4];
    #pragma unroll
    for (int mt = 0; mt < 2; mt++)
        #pragma unroll
        for (int nt = 0; nt < 2; nt++)
            #pragma unroll
            for (int r = 0; r < 4; r++) acc[mt][nt][r] = 0.f;

    auto stage = [&](int c, int buf) {
        unsigned* Ah = (unsigned*)(smem + buf * PG_BUF);
        unsigned* Al = (unsigned*)(smem + buf * PG_BUF + 9216);
        unsigned* Bh = (unsigned*)(smem + buf * PG_BUF + 18432);
        unsigned* Bl = (unsigned*)(smem + buf * PG_BUF + 27648);
        #pragma unroll
        for (int i = 0; i < 2; i++) {
            int u = tid + i * 256;
            int row = u >> 3, kp = (u & 7) * 4;
            unsigned sa = (unsigned)(i0 + row) * PK_STRIDE + c * 32 + kp;
            unsigned sb = (unsigned)(j0 + row) * PK_STRIDE + c * 32 + kp;
            cp16(s2u(&Ah[row * AS_STRIDE + kp]), &g_pAhi[sa]);
            cp16(s2u(&Al[row * AS_STRIDE + kp]), &g_pAlo[sa]);
            cp16(s2u(&Bh[row * AS_STRIDE + kp]), &g_pBhi[sb]);
            cp16(s2u(&Bl[row * AS_STRIDE + kp]), &g_pBlo[sb]);
        }
        asm volatile("cp.async.commit_group;\n" ::: "memory");
    };

    stage(bz, 0);

    int buf = 0;
    for (int c = bz; c < PK_CHUNKS; c += PK_SLICES, buf ^= 1) {
        int nc = c + PK_SLICES;
        if (nc < PK_CHUNKS) {
            stage(nc, buf ^ 1);
            asm volatile("cp.async.wait_group 1;\n" ::: "memory");
        } else {
            asm volatile("cp.async.wait_group 0;\n" ::: "memory");
        }
        __syncthreads();

        const unsigned sA0 = s2u(smem + buf * PG_BUF) + laneoff;
        const unsigned sA1 = sA0 + 9216;
        unsigned* Bh = (unsigned*)(smem + buf * PG_BUF + 18432);
        unsigned* Bl = (unsigned*)(smem + buf * PG_BUF + 27648);

        #pragma unroll
        for (int ks = 0; ks < 4; ks++) {
            const int cw = ks * 8 + tig;
            unsigned b[2][2][2];
            #pragma unroll
            for (int nt = 0; nt < 2; nt++) {
                int n = wn * 16 + nt * 8 + gid;
                b[nt][0][0] = Bh[n * AS_STRIDE + cw];
                b[nt][0][1] = Bh[n * AS_STRIDE + cw + 4];
                b[nt][1][0] = Bl[n * AS_STRIDE + cw];
                b[nt][1][1] = Bl[n * AS_STRIDE + cw + 4];
            }
            unsigned a[2][2][4];
            #pragma unroll
            for (int mt = 0; mt < 2; mt++) {
                unsigned aoff = (((wm * 32 + mt * 16) * AS_STRIDE) + ks * 8) * 4;
                ldsm4(a[mt][0], sA0 + aoff);
                ldsm4(a[mt][1], sA1 + aoff);
            }
            #pragma unroll
            for (int mt = 0; mt < 2; mt++)
                #pragma unroll
                for (int nt = 0; nt < 2; nt++)
                    mma16816(acc[mt][nt], a[mt][0], b[nt][0]);
            #pragma unroll
            for (int mt = 0; mt < 2; mt++)
                #pragma unroll
                for (int nt = 0; nt < 2; nt++)
                    mma16816(acc[mt][nt], a[mt][0], b[nt][1]);
            #pragma unroll
            for (int mt = 0; mt < 2; mt++)
                #pragma unroll
                for (int nt = 0; nt < 2; nt++)
                    mma16816(acc[mt][nt], a[mt][1], b[nt][0]);
        }
        __syncthreads();
    }

    #pragma unroll
    for (int mt = 0; mt < 2; mt++) {
        int r0 = i0 + wm * 32 + mt * 16 + gid;
        #pragma unroll
        for (int nt = 0; nt < 2; nt++) {
            int c = j0 + wn * 16 + nt * 8 + tig * 2;
            *(float2*)&g_spart[bz][r0][c]     = make_float2(acc[mt][nt][0], acc[mt][nt][1]);
            *(float2*)&g_spart[bz][r0 + 8][c] = make_float2(acc[mt][nt][2], acc[mt][nt][3]);
        }
    }
}

// ============================================================
// K4: assemble score + log_softmax + classes tail.
// ============================================================
__global__ void k_softmax(float* __restrict__ out, int out_size)
{
    const int i = blockIdx.x;
    const int j = threadIdx.x;
    __shared__ float red[256];

    float s = 0.f;
    #pragma unroll
    for (int z = 0; z < PK_SLICES; z++) s += g_spart[z][i][j];

    float H0 = 0.5f * (float)T * LOG_2PIE;
    float H1 = H0;
    float M0 = 0.f, M1 = 0.f;
    #pragma unroll
    for (int b = 0; b < 18; b++) {
        H0 += g_Hpart[b][i];
        H1 += g_Hpart[b][NEP + j];
        M0 += g_Mpart[b][i];
        M1 += g_Mpart[b][NEP + j];
    }
    float score = 0.5f * (s + M0 + M1) - (float)T + H0 + H1;
    float v = -score;

    red[j] = v;
    __syncthreads();
    for (int st = 128; st > 0; st >>= 1) {
        if (j < st) red[j] = fmaxf(red[j], red[j + st]);
        __syncthreads();
    }
    float mx = red[0];
    __syncthreads();
    float ex = expf(v - mx);
    red[j] = ex;
    __syncthreads();
    for (int st = 128; st > 0; st >>= 1) {
        if (j < st) red[j] += red[j + st];
        __syncthreads();
    }
    float lse = mx + logf(red[0]);
    out[(size_t)i * NEP + j] = v - lse;

    if (j == 0 && NEP * NEP + i < out_size)
        out[NEP * NEP + i] = (float)i;
}

// ============================================================
extern "C" void kernel_launch(void* const* d_in, const int* in_sizes, int n_in,
                              void* d_out, int out_size)
{
    const float* train_inputs  = (const float*)d_in[0];
    const float* train_targets = (const float*)d_in[1];
    const float* test_inputs   = (const float*)d_in[2];
    const float* test_targets  = (const float*)d_in[3];
    const float* W_fe          = (const float*)d_in[4];
    const float* b_fe          = (const float*)d_in[5];
    const float* W_lv          = (const float*)d_in[6];
    const float* b_lv          = (const float*)d_in[7];
    float* out = (float*)d_out;

    const int smem_fgemm = 2 * FG_BUF;           // 143360
    const int smem_lv    = 2 * LV_BUF;           // 73728
    const int smem_pg    = 2 * PG_BUF;           // 73728
    cudaFuncSetAttribute(k_fgemm,  cudaFuncAttributeMaxDynamicSharedMemorySize, smem_fgemm);
    cudaFuncSetAttribute(k_lvgemm, cudaFuncAttributeMaxDynamicSharedMemorySize, smem_lv);
    cudaFuncSetAttribute(k_pgemm,  cudaFuncAttributeMaxDynamicSharedMemorySize, smem_pg);

    k_prep<<<5028, 256>>>(train_inputs, test_inputs, W_fe, W_lv,
                          train_targets, test_targets);
    k_fgemm<<<FG_GRID, 256, smem_fgemm>>>(b_fe);
    k_lvgemm<<<dim3(18, 8), 256, smem_lv>>>(b_lv);
    k_pgemm<<<dim3(4, 4, PK_SLICES), 256, smem_pg>>>();
    k_softmax<<<NEP, 256>>>(out, out_size);
}

// round 17
// speedup vs baseline: 1.1362x; 1.0681x over previous
#include <cuda_runtime.h>
#include <cuda_bf16.h>
#include <math.h>

#define NEP 256
#define NS  32
#define DIN 512
#define DF  512
#define T   1026
#define TT  513

#define LOG_2PIE 2.8378770664093453f

// K geometry for the logvar GEMM: K=1026 -> 513 k-pairs -> pad to 544 (17 chunks of 32)
#define LV_KP   544
#define LV_NPAD 1152   // 18 tiles of 64

// pair-GEMM K geometry: K = 4*1026 = 4104 -> 2052 pairs -> pad to 2080 (65 chunks of 32)
#define PK_STRIDE 2080
#define PK_CHUNKS 65
#define PK_SLICES 9

// -------- device scratch (no allocations allowed) --------
__device__ float g_mu [2][NEP][T];   // z (mu)
__device__ float g_Hpart[18][512];   // per-Ntile partial sums of lv per row (row = set*256+e)
__device__ float g_Mpart[18][512];   // per-Ntile partial sums of m^2*exp(-lv) per row
__device__ float g_spart[PK_SLICES][NEP][NEP]; // pairwise score partials per K-slice

// bf16 split operands. Inputs: [set][8192 rows][256 k-pair words] (K contiguous)
__device__ __align__(16) unsigned g_ihi[2][8192 * 256];
__device__ __align__(16) unsigned g_ilo[2][8192 * 256];
// W_fe split, k-pair interleaved: word (k2, n) holds halves (k=2*k2, 2*k2+1) of column n
__device__ __align__(16) unsigned g_wphi[256 * 512];
__device__ __align__(16) unsigned g_wplo[256 * 512];
// z split: [512 rows (set*256+e)][544 k-pair words]; pad never written (zero-init)
__device__ __align__(16) unsigned g_zhi[512 * LV_KP];
__device__ __align__(16) unsigned g_zlo[512 * LV_KP];
// W_lv split (padded)
__device__ __align__(16) unsigned g_wlvh[LV_KP * LV_NPAD];
__device__ __align__(16) unsigned g_wlvl[LV_KP * LV_NPAD];
// pairwise feature rows, bf16 split, k = 4*n + f (f=0..3), pad zero-init
__device__ __align__(16) unsigned g_pAhi[NEP * PK_STRIDE];
__device__ __align__(16) unsigned g_pAlo[NEP * PK_STRIDE];
__device__ __align__(16) unsigned g_pBhi[NEP * PK_STRIDE];
__device__ __align__(16) unsigned g_pBlo[NEP * PK_STRIDE];

// ============================================================
__device__ __forceinline__ void split1(float x, unsigned short& h, unsigned short& l)
{
    __nv_bfloat16 bh = __float2bfloat16(x);
    float r = x - __bfloat162float(bh);
    __nv_bfloat16 bl = __float2bfloat16(r);
    h = __bfloat16_as_ushort(bh);
    l = __bfloat16_as_ushort(bl);
}

__device__ __forceinline__ unsigned splitpair(float x0, float x1, unsigned& lo)
{
    unsigned short h0, l0, h1, l1;
    split1(x0, h0, l0);
    split1(x1, h1, l1);
    lo = (unsigned)l0 | ((unsigned)l1 << 16);
    return (unsigned)h0 | ((unsigned)h1 << 16);
}

__device__ __forceinline__ void cp16(unsigned saddr, const void* g)
{
    asm volatile("cp.async.cg.shared.global [%0], [%1], 16;\n" :: "r"(saddr), "l"(g));
}
__device__ __forceinline__ unsigned s2u(const void* p)
{
    return (unsigned)__cvta_generic_to_shared(p);
}
__device__ __forceinline__ void ldsm4(unsigned* r, unsigned addr)
{
    asm volatile("ldmatrix.sync.aligned.m8n8.x4.shared.b16 {%0,%1,%2,%3}, [%4];"
                 : "=r"(r[0]), "=r"(r[1]), "=r"(r[2]), "=r"(r[3]) : "r"(addr));
}

// ============================================================
// merged prep, 4x-vectorized (round-11 proven config)
// ============================================================
__global__ void k_prep(const float* __restrict__ trin, const float* __restrict__ tein,
                       const float* __restrict__ Wfe, const float* __restrict__ Wlv,
                       const float* __restrict__ trtg, const float* __restrict__ tetg)
{
    const int b = blockIdx.x;
    const int tid = threadIdx.x;

    if (b < 4096) {
        const int set = b >> 11;
        const unsigned w0 = ((unsigned)(b & 2047) * 256 + tid) * 4;
        const float4* src = (const float4*)(set ? tein : trin);
        float4 v0 = src[w0 >> 1];
        float4 v1 = src[(w0 >> 1) + 1];
        unsigned hi0, hi1, hi2, hi3, lo0, lo1, lo2, lo3;
        hi0 = splitpair(v0.x, v0.y, lo0);
        hi1 = splitpair(v0.z, v0.w, lo1);
        hi2 = splitpair(v1.x, v1.y, lo2);
        hi3 = splitpair(v1.z, v1.w, lo3);
        *(uint4*)&g_ihi[set][w0] = make_uint4(hi0, hi1, hi2, hi3);
        *(uint4*)&g_ilo[set][w0] = make_uint4(lo0, lo1, lo2, lo3);
    } else if (b < 4352) {
        const unsigned w = ((unsigned)(b - 4096) * 256 + tid) * 2;
        unsigned hi[2], lo[2];
        #pragma unroll
        for (int i = 0; i < 2; i++) {
            unsigned ww = w + i;
            int k2 = ww >> 9;
            int n  = ww & 511;
            float x0 = Wfe[(size_t)(2 * k2) * DF + n];
            float x1 = Wfe[(size_t)(2 * k2 + 1) * DF + n];
            hi[i] = splitpair(x0, x1, lo[i]);
        }
        *(uint2*)&g_wphi[w] = make_uint2(hi[0], hi[1]);
        *(uint2*)&g_wplo[w] = make_uint2(lo[0], lo[1]);
    } else if (b < 4964) {
        const unsigned idx = ((unsigned)(b - 4352) * 256 + tid) * 4;
        const int k2 = idx / LV_NPAD;
        const int n0 = idx % LV_NPAD;
        const int k = 2 * k2;
        unsigned hi[4], lo[4];
        #pragma unroll
        for (int i = 0; i < 4; i++) {
            int n = n0 + i;
            float x0 = (k     < T && n < T) ? Wlv[(size_t)k * T + n]       : 0.f;
            float x1 = (k + 1 < T && n < T) ? Wlv[(size_t)(k + 1) * T + n] : 0.f;
            hi[i] = splitpair(x0, x1, lo[i]);
        }
        *(uint4*)&g_wlvh[idx] = make_uint4(hi[0], hi[1], hi[2], hi[3]);
        *(uint4*)&g_wlvl[idx] = make_uint4(lo[0], lo[1], lo[2], lo[3]);
    } else {
        const int w = (b - 4964) * 8 + (tid >> 5);
        const int lane = tid & 31;
        const int set = w >> 8, e = w & 255;
        const float* tg = (set ? tetg : trtg) + (size_t)e * NS;
        float x = tg[lane];
        float s = x;
        #pragma unroll
        for (int off = 16; off > 0; off >>= 1) s += __shfl_xor_sync(0xffffffffu, s, off);
        float m = s * (1.f / NS);
        float d = x - m;
        float q = d * d;
        #pragma unroll
        for (int off = 16; off > 0; off >>= 1) q += __shfl_xor_sync(0xffffffffu, q, off);
        if (lane == 0) {
            float sd = sqrtf(q * (1.f / (NS - 1)));
            g_mu[set][e][0]  = m;
            g_mu[set][e][TT] = sd;
            unsigned short* zh = (unsigned short*)g_zhi;
            unsigned short* zl = (unsigned short*)g_zlo;
            const unsigned base = (unsigned)(set * 256 + e) * (2 * LV_KP);
            unsigned short h0, l0, h1, l1;
            split1(m,  h0, l0);
            split1(sd, h1, l1);
            zh[base + 0]  = h0;  zl[base + 0]  = l0;
            zh[base + TT] = h1;  zl[base + TT] = l1;
        }
    }
}

// ============================================================
// mma helper
// ============================================================
__device__ __forceinline__ void mma16816(float* d, const unsigned* a, const unsigned* b)
{
    asm volatile(
        "mma.sync.aligned.m16n8k16.row.col.f32.bf16.bf16.f32 "
        "{%0,%1,%2,%3}, {%4,%5,%6,%7}, {%8,%9}, {%0,%1,%2,%3};\n"
        : "+f"(d[0]), "+f"(d[1]), "+f"(d[2]), "+f"(d[3])
        : "r"(a[0]), "r"(a[1]), "r"(a[2]), "r"(a[3]), "r"(b[0]), "r"(b[1]));
}

#define AS_STRIDE 36   // uint32 words per 32-word-wide smem row (+4 pad)
#define BS2 264        // fgemm B row stride (256 + 8): bank step 8*tig+gid -> conflict-free

// per-lane ldmatrix address offset (bytes) within an A tile
#define LDSM_LANE_OFF(lid) ((((lid) & 15) * AS_STRIDE + ((lid) >> 4) * 4) * 4)

// ============================================================
// K1: feature GEMM (HMMA), CTA tile 128x256 (warp tile 64x64).
// cp.async double-buffered, A via ldmatrix, term-pass ordered,
// conflict-free B (stride 264). grid (2,64,2) = 256 CTAs.
// Fused bias/relu/mean/std epilogue + z-split.
// ============================================================
#define FG_BUF 104448  // A hi/lo 2*18432 + B hi/lo 2*33792

__global__ __launch_bounds__(256, 1)
void k_fgemm(const float* __restrict__ bfe)
{
    extern __shared__ unsigned char smem[];
    const int ct  = blockIdx.x;      // 256-wide feature tile (0..1)
    const int eg  = blockIdx.y;
    const int set = blockIdx.z;
    const int tid = threadIdx.x;
    const int wid = tid >> 5;
    const int lid = tid & 31;
    const int wm  = wid >> 2;        // 0..1 : 64-row warp tile
    const int wn  = wid & 3;         // 0..3 : 64-col warp tile
    const int gid = lid >> 2;
    const int tig = lid & 3;
    const unsigned laneoff = LDSM_LANE_OFF(lid);

    const unsigned* gih = g_ihi[set];
    const unsigned* gil = g_ilo[set];

    float acc[4][8][4];
    #pragma unroll
    for (int mt = 0; mt < 4; mt++)
        #pragma unroll
        for (int nt = 0; nt < 8; nt++)
            #pragma unroll
            for (int r = 0; r < 4; r++) acc[mt][nt][r] = 0.f;

    auto stage = [&](int c, int buf) {
        unsigned* Aw0 = (unsigned*)(smem + buf * FG_BUF);
        unsigned* Aw1 = (unsigned*)(smem + buf * FG_BUF + 18432);
        unsigned* Bw0 = (unsigned*)(smem + buf * FG_BUF + 36864);
        unsigned* Bw1 = (unsigned*)(smem + buf * FG_BUF + 70656);
        #pragma unroll
        for (int i = 0; i < 4; i++) {
            int u = tid + i * 256;                 // 1024 16B units per term
            int row = u >> 3, kp = (u & 7) * 4;
            unsigned srci = (unsigned)(eg * 128 + row) * 256 + c * 32 + kp;
            cp16(s2u(&Aw0[row * AS_STRIDE + kp]), &gih[srci]);
            cp16(s2u(&Aw1[row * AS_STRIDE + kp]), &gil[srci]);
        }
        #pragma unroll
        for (int i = 0; i < 8; i++) {
            int u = tid + i * 256;                 // 2048 units per term
            int k2 = u >> 6, nl = (u & 63) * 4;
            unsigned srci = (unsigned)(c * 32 + k2) * 512 + ct * 256 + nl;
            cp16(s2u(&Bw0[k2 * BS2 + nl]), &g_wphi[srci]);
            cp16(s2u(&Bw1[k2 * BS2 + nl]), &g_wplo[srci]);
        }
        asm volatile("cp.async.commit_group;\n" ::: "memory");
    };

    stage(0, 0);

    for (int chunk = 0; chunk < 8; chunk++) {
        if (chunk < 7) {
            stage(chunk + 1, (chunk + 1) & 1);
            asm volatile("cp.async.wait_group 1;\n" ::: "memory");
        } else {
            asm volatile("cp.async.wait_group 0;\n" ::: "memory");
        }
        __syncthreads();

        const int buf = chunk & 1;
        const unsigned sA0 = s2u(smem + buf * FG_BUF) + laneoff;
        const unsigned sA1 = sA0 + 18432;
        unsigned* Bw0 = (unsigned*)(smem + buf * FG_BUF + 36864);
        unsigned* Bw1 = (unsigned*)(smem + buf * FG_BUF + 70656);

        #pragma unroll
        for (int ks = 0; ks < 4; ks++) {
            const int cw = ks * 8 + tig;
            unsigned a[4][2][4];
            #pragma unroll
            for (int mt = 0; mt < 4; mt++) {
                unsigned aoff = (((wm * 64 + mt * 16) * AS_STRIDE) + ks * 8) * 4;
                ldsm4(a[mt][0], sA0 + aoff);
                ldsm4(a[mt][1], sA1 + aoff);
            }
            #pragma unroll
            for (int half = 0; half < 2; half++) {
                unsigned b[4][2][2];
                #pragma unroll
                for (int nl = 0; nl < 4; nl++) {
                    int n = wn * 64 + (half * 4 + nl) * 8 + gid;
                    b[nl][0][0] = Bw0[cw * BS2 + n];
                    b[nl][0][1] = Bw0[(cw + 4) * BS2 + n];
                    b[nl][1][0] = Bw1[cw * BS2 + n];
                    b[nl][1][1] = Bw1[(cw + 4) * BS2 + n];
                }
                #pragma unroll
                for (int mt = 0; mt < 4; mt++)
                    #pragma unroll
                    for (int nl = 0; nl < 4; nl++)
                        mma16816(acc[mt][half * 4 + nl], a[mt][0], b[nl][0]);
                #pragma unroll
                for (int mt = 0; mt < 4; mt++)
                    #pragma unroll
                    for (int nl = 0; nl < 4; nl++)
                        mma16816(acc[mt][half * 4 + nl], a[mt][0], b[nl][1]);
                #pragma unroll
                for (int mt = 0; mt < 4; mt++)
                    #pragma unroll
                    for (int nl = 0; nl < 4; nl++)
                        mma16816(acc[mt][half * 4 + nl], a[mt][1], b[nl][0]);
            }
        }
        __syncthreads();
    }

    float* Cs = (float*)smem;     // [128][264]
    #pragma unroll
    for (int mt = 0; mt < 4; mt++) {
        int r0 = wm * 64 + mt * 16 + gid;
        #pragma unroll
        for (int nt = 0; nt < 8; nt++) {
            int c = wn * 64 + nt * 8 + tig * 2;
            *(float2*)&Cs[r0 * BS2 + c]       = make_float2(acc[mt][nt][0], acc[mt][nt][1]);
            *(float2*)&Cs[(r0 + 8) * BS2 + c] = make_float2(acc[mt][nt][2], acc[mt][nt][3]);
        }
    }
    __syncthreads();

    {
        const int j = tid;               // 0..255 : feature column within tile
        const int f = ct * 256 + j;
        const float bias = bfe[f];
        unsigned short* zh = (unsigned short*)g_zhi;
        unsigned short* zl = (unsigned short*)g_zlo;
        #pragma unroll
        for (int ep = 0; ep < 4; ep++) {
            float s = 0.f, ss = 0.f;
            #pragma unroll
            for (int m = 0; m < NS; m++) {
                float v = Cs[(ep * 32 + m) * BS2 + j] + bias;
                v = fmaxf(v, 0.f);
                s += v;
                ss = fmaf(v, v, ss);
            }
            float mean = s * (1.f / NS);
            float var  = (ss - s * mean) * (1.f / (NS - 1));
            float stdv = sqrtf(fmaxf(var, 0.f));
            int e = eg * 4 + ep;
            g_mu[set][e][1 + f]      = mean;
            g_mu[set][e][TT + 1 + f] = stdv;
            const unsigned base = (unsigned)(set * 256 + e) * (2 * LV_KP);
            unsigned short h0, l0, h1, l1;
            split1(mean, h0, l0);
            split1(stdv, h1, l1);
            zh[base + 1 + f]      = h0;  zl[base + 1 + f]      = l0;
            zh[base + TT + 1 + f] = h1;  zl[base + TT + 1 + f] = l1;
        }
    }
}

// ============================================================
// K2: logvar GEMM (HMMA), B stride 72 (conflict-free), term-pass ordered.
// Block 64x64, grid (18,8) = 144 blocks, 256 threads.
// Epilogue: +b_lv, clip, pairwise FEATURES (bf16-split) + H/M partials.
// ============================================================
#define LVB_STRIDE 72
#define LV_BUF 36864   // A 2*9216 + B 2*9216

__global__ __launch_bounds__(256, 1)
void k_lvgemm(const float* __restrict__ blv)
{
    extern __shared__ unsigned char smem[];

    const int bn  = blockIdx.x;
    const int bm  = blockIdx.y;
    const int tid = threadIdx.x;
    const int wid = tid >> 5;
    const int lid = tid & 31;
    const int wm  = wid >> 2;
    const int wn  = wid & 3;
    const int gid = lid >> 2;
    const int tig = lid & 3;
    const unsigned laneoff = LDSM_LANE_OFF(lid);

    float acc[2][2][4];
    #pragma unroll
    for (int mt = 0; mt < 2; mt++)
        #pragma unroll
        for (int nt = 0; nt < 2; nt++)
            #pragma unroll
            for (int r = 0; r < 4; r++) acc[mt][nt][r] = 0.f;

    auto stage = [&](int c, int buf) {
        unsigned* Aw0 = (unsigned*)(smem + buf * LV_BUF);
        unsigned* Aw1 = (unsigned*)(smem + buf * LV_BUF + 9216);
        unsigned* Bw0 = (unsigned*)(smem + buf * LV_BUF + 18432);
        unsigned* Bw1 = (unsigned*)(smem + buf * LV_BUF + 27648);
        #pragma unroll
        for (int i = 0; i < 2; i++) {
            int u = tid + i * 256;
            int row = u >> 3, kp = (u & 7) * 4;
            unsigned srci = (unsigned)(bm * 64 + row) * LV_KP + c * 32 + kp;
            cp16(s2u(&Aw0[row * AS_STRIDE + kp]), &g_zhi[srci]);
            cp16(s2u(&Aw1[row * AS_STRIDE + kp]), &g_zlo[srci]);
        }
        #pragma unroll
        for (int i = 0; i < 2; i++) {
            int u = tid + i * 256;
            int k2 = u >> 4, nl = (u & 15) * 4;
            unsigned srci = (unsigned)(c * 32 + k2) * LV_NPAD + bn * 64 + nl;
            cp16(s2u(&Bw0[k2 * LVB_STRIDE + nl]), &g_wlvh[srci]);
            cp16(s2u(&Bw1[k2 * LVB_STRIDE + nl]), &g_wlvl[srci]);
        }
        asm volatile("cp.async.commit_group;\n" ::: "memory");
    };

    stage(0, 0);

    for (int chunk = 0; chunk < 17; chunk++) {
        if (chunk < 16) {
            stage(chunk + 1, (chunk + 1) & 1);
            asm volatile("cp.async.wait_group 1;\n" ::: "memory");
        } else {
            asm volatile("cp.async.wait_group 0;\n" ::: "memory");
        }
        __syncthreads();

        const int buf = chunk & 1;
        const unsigned sA0 = s2u(smem + buf * LV_BUF) + laneoff;
        const unsigned sA1 = sA0 + 9216;
        unsigned* Bw0 = (unsigned*)(smem + buf * LV_BUF + 18432);
        unsigned* Bw1 = (unsigned*)(smem + buf * LV_BUF + 27648);

        #pragma unroll
        for (int ks = 0; ks < 4; ks++) {
            const int cw = ks * 8 + tig;
            unsigned b[2][2][2];
            #pragma unroll
            for (int nt = 0; nt < 2; nt++) {
                int n = wn * 16 + nt * 8 + gid;
                b[nt][0][0] = Bw0[cw * LVB_STRIDE + n];
                b[nt][0][1] = Bw0[(cw + 4) * LVB_STRIDE + n];
                b[nt][1][0] = Bw1[cw * LVB_STRIDE + n];
                b[nt][1][1] = Bw1[(cw + 4) * LVB_STRIDE + n];
            }
            unsigned a[2][2][4];
            #pragma unroll
            for (int mt = 0; mt < 2; mt++) {
                unsigned aoff = (((wm * 32 + mt * 16) * AS_STRIDE) + ks * 8) * 4;
                ldsm4(a[mt][0], sA0 + aoff);
                ldsm4(a[mt][1], sA1 + aoff);
            }
            #pragma unroll
            for (int mt = 0; mt < 2; mt++)
                #pragma unroll
                for (int nt = 0; nt < 2; nt++)
                    mma16816(acc[mt][nt], a[mt][0], b[nt][0]);
            #pragma unroll
            for (int mt = 0; mt < 2; mt++)
                #pragma unroll
                for (int nt = 0; nt < 2; nt++)
                    mma16816(acc[mt][nt], a[mt][0], b[nt][1]);
            #pragma unroll
            for (int mt = 0; mt < 2; mt++)
                #pragma unroll
                for (int nt = 0; nt < 2; nt++)
                    mma16816(acc[mt][nt], a[mt][1], b[nt][0]);
        }
        __syncthreads();
    }

    float* Cs = (float*)smem;                  // [64][72]
    float* hq = (float*)(smem + 18432);        // [64][2]
    float* mq = (float*)(smem + 18944);        // [64][2]
    #pragma unroll
    for (int mt = 0; mt < 2; mt++) {
        int r0 = wm * 32 + mt * 16 + gid;
        #pragma unroll
        for (int nt = 0; nt < 2; nt++) {
            int c = wn * 16 + nt * 8 + tig * 2;
            *(float2*)&Cs[r0 * LVB_STRIDE + c]       = make_float2(acc[mt][nt][0], acc[mt][nt][1]);
            *(float2*)&Cs[(r0 + 8) * LVB_STRIDE + c] = make_float2(acc[mt][nt][2], acc[mt][nt][3]);
        }
    }
    __syncthreads();

    {
        const int j    = tid & 63;
        const int rg   = tid >> 6;
        const int w2   = (tid >> 5) & 1;
        const int lane = tid & 31;
        const int n = bn * 64 + j;
        const bool valid = (n < T);
        const float bias = valid ? blv[n] : 0.f;
        const int set_blk = (bm >= 4);
        const int ebase = (bm & 3) * 64;

        #pragma unroll
        for (int rr = 0; rr < 16; rr++) {
            int r = rg * 16 + rr;
            float lv = fminf(fmaxf(Cs[r * LVB_STRIDE + j] + bias, -9.f), -2.f);
            float h = valid ? lv : 0.f;
            float mm = 0.f;
            if (valid) {
                int e = ebase + r;
                float m   = g_mu[set_blk][e][n];
                float elv = expf(lv);
                float eml = expf(-lv);
                mm = m * m * eml;
                float f0, f1, f2, f3;
                if (set_blk == 0) {
                    f0 = elv + m * m;  f1 = eml;         f2 = m * eml;    f3 = m;
                } else {
                    f0 = eml;          f1 = elv + m * m; f2 = -2.f * m;   f3 = -2.f * m * eml;
                }
                unsigned lo0, lo1, hi0, hi1;
                hi0 = splitpair(f0, f1, lo0);
                hi1 = splitpair(f2, f3, lo1);
                unsigned widx = (unsigned)e * PK_STRIDE + 2 * n;
                if (set_blk == 0) {
                    *(uint2*)&g_pAhi[widx] = make_uint2(hi0, hi1);
                    *(uint2*)&g_pAlo[widx] = make_uint2(lo0, lo1);
                } else {
                    *(uint2*)&g_pBhi[widx] = make_uint2(hi0, hi1);
                    *(uint2*)&g_pBlo[widx] = make_uint2(lo0, lo1);
                }
            }
            #pragma unroll
            for (int off = 16; off > 0; off >>= 1) {
                h  += __shfl_down_sync(0xffffffffu, h,  off);
                mm += __shfl_down_sync(0xffffffffu, mm, off);
            }
            if (lane == 0) { hq[r * 2 + w2] = h; mq[r * 2 + w2] = mm; }
        }
    }
    __syncthreads();
    if (tid < 64) {
        g_Hpart[bn][bm * 64 + tid] = hq[tid * 2] + hq[tid * 2 + 1];
        g_Mpart[bn][bm * 64 + tid] = mq[tid * 2] + mq[tid * 2 + 1];
    }
}

// ============================================================
// K3: pairwise GEMM (HMMA), term-pass ordered, A via ldmatrix.
// spart[z][i][j] over chunks {z, z+9, ...} < 65. grid (4,4,9) = 144.
// ============================================================
#define PG_BUF 36864

__global__ __launch_bounds__(256, 1)
void k_pgemm()
{
    extern __shared__ unsigned char smem[];
    const int j0  = blockIdx.x * 64;
    const int i0  = blockIdx.y * 64;
    const int bz  = blockIdx.z;
    const int tid = threadIdx.x;
    const int wid = tid >> 5;
    const int lid = tid & 31;
    const int wm  = wid >> 2;
    const int wn  = wid & 3;
    const int gid = lid >> 2;
    const int tig = lid & 3;
    const unsigned laneoff = LDSM_LANE_OFF(lid);

    float acc[2][2][4];
    #pragma unroll
    for (int mt = 0; mt < 2; mt++)
        #pragma unroll
        for (int nt = 0; nt < 2; nt++)
            #pragma unroll
            for (int r = 0; r < 4; r++) acc[mt][nt][r] = 0.f;

    auto stage = [&](int c, int buf) {
        unsigned* Ah = (unsigned*)(smem + buf * PG_BUF);
        unsigned* Al = (unsigned*)(smem + buf * PG_BUF + 9216);
        unsigned* Bh = (unsigned*)(smem + buf * PG_BUF + 18432);
        unsigned* Bl = (unsigned*)(smem + buf * PG_BUF + 27648);
        #pragma unroll
        for (int i = 0; i < 2; i++) {
            int u = tid + i * 256;
            int row = u >> 3, kp = (u & 7) * 4;
            unsigned sa = (unsigned)(i0 + row) * PK_STRIDE + c * 32 + kp;
            unsigned sb = (unsigned)(j0 + row) * PK_STRIDE + c * 32 + kp;
            cp16(s2u(&Ah[row * AS_STRIDE + kp]), &g_pAhi[sa]);
            cp16(s2u(&Al[row * AS_STRIDE + kp]), &g_pAlo[sa]);
            cp16(s2u(&Bh[row * AS_STRIDE + kp]), &g_pBhi[sb]);
            cp16(s2u(&Bl[row * AS_STRIDE + kp]), &g_pBlo[sb]);
        }
        asm volatile("cp.async.commit_group;\n" ::: "memory");
    };

    stage(bz, 0);

    int buf = 0;
    for (int c = bz; c < PK_CHUNKS; c += PK_SLICES, buf ^= 1) {
        int nc = c + PK_SLICES;
        if (nc < PK_CHUNKS) {
            stage(nc, buf ^ 1);
            asm volatile("cp.async.wait_group 1;\n" ::: "memory");
        } else {
            asm volatile("cp.async.wait_group 0;\n" ::: "memory");
        }
        __syncthreads();

        const unsigned sA0 = s2u(smem + buf * PG_BUF) + laneoff;
        const unsigned sA1 = sA0 + 9216;
        unsigned* Bh = (unsigned*)(smem + buf * PG_BUF + 18432);
        unsigned* Bl = (unsigned*)(smem + buf * PG_BUF + 27648);

        #pragma unroll
        for (int ks = 0; ks < 4; ks++) {
            const int cw = ks * 8 + tig;
            unsigned b[2][2][2];
            #pragma unroll
            for (int nt = 0; nt < 2; nt++) {
                int n = wn * 16 + nt * 8 + gid;
                b[nt][0][0] = Bh[n * AS_STRIDE + cw];
                b[nt][0][1] = Bh[n * AS_STRIDE + cw + 4];
                b[nt][1][0] = Bl[n * AS_STRIDE + cw];
                b[nt][1][1] = Bl[n * AS_STRIDE + cw + 4];
            }
            unsigned a[2][2][4];
            #pragma unroll
            for (int mt = 0; mt < 2; mt++) {
                unsigned aoff = (((wm * 32 + mt * 16) * AS_STRIDE) + ks * 8) * 4;
                ldsm4(a[mt][0], sA0 + aoff);
                ldsm4(a[mt][1], sA1 + aoff);
            }
            #pragma unroll
            for (int mt = 0; mt < 2; mt++)
                #pragma unroll
                for (int nt = 0; nt < 2; nt++)
                    mma16816(acc[mt][nt], a[mt][0], b[nt][0]);
            #pragma unroll
            for (int mt = 0; mt < 2; mt++)
                #pragma unroll
                for (int nt = 0; nt < 2; nt++)
                    mma16816(acc[mt][nt], a[mt][0], b[nt][1]);
            #pragma unroll
            for (int mt = 0; mt < 2; mt++)
                #pragma unroll
                for (int nt = 0; nt < 2; nt++)
                    mma16816(acc[mt][nt], a[mt][1], b[nt][0]);
        }
        __syncthreads();
    }

    #pragma unroll
    for (int mt = 0; mt < 2; mt++) {
        int r0 = i0 + wm * 32 + mt * 16 + gid;
        #pragma unroll
        for (int nt = 0; nt < 2; nt++) {
            int c = j0 + wn * 16 + nt * 8 + tig * 2;
            *(float2*)&g_spart[bz][r0][c]     = make_float2(acc[mt][nt][0], acc[mt][nt][1]);
            *(float2*)&g_spart[bz][r0 + 8][c] = make_float2(acc[mt][nt][2], acc[mt][nt][3]);
        }
    }
}

// ============================================================
// K4: assemble score + log_softmax + classes tail.
// ============================================================
__global__ void k_softmax(float* __restrict__ out, int out_size)
{
    const int i = blockIdx.x;
    const int j = threadIdx.x;
    __shared__ float red[256];

    float s = 0.f;
    #pragma unroll
    for (int z = 0; z < PK_SLICES; z++) s += g_spart[z][i][j];

    float H0 = 0.5f * (float)T * LOG_2PIE;
    float H1 = H0;
    float M0 = 0.f, M1 = 0.f;
    #pragma unroll
    for (int b = 0; b < 18; b++) {
        H0 += g_Hpart[b][i];
        H1 += g_Hpart[b][NEP + j];
        M0 += g_Mpart[b][i];
        M1 += g_Mpart[b][NEP + j];
    }
    float score = 0.5f * (s + M0 + M1) - (float)T + H0 + H1;
    float v = -score;

    red[j] = v;
    __syncthreads();
    for (int st = 128; st > 0; st >>= 1) {
        if (j < st) red[j] = fmaxf(red[j], red[j + st]);
        __syncthreads();
    }
    float mx = red[0];
    __syncthreads();
    float ex = expf(v - mx);
    red[j] = ex;
    __syncthreads();
    for (int st = 128; st > 0; st >>= 1) {
        if (j < st) red[j] += red[j + st];
        __syncthreads();
    }
    float lse = mx + logf(red[0]);
    out[(size_t)i * NEP + j] = v - lse;

    if (j == 0 && NEP * NEP + i < out_size)
        out[NEP * NEP + i] = (float)i;
}

// ============================================================
extern "C" void kernel_launch(void* const* d_in, const int* in_sizes, int n_in,
                              void* d_out, int out_size)
{
    const float* train_inputs  = (const float*)d_in[0];
    const float* train_targets = (const float*)d_in[1];
    const float* test_inputs   = (const float*)d_in[2];
    const float* test_targets  = (const float*)d_in[3];
    const float* W_fe          = (const float*)d_in[4];
    const float* b_fe          = (const float*)d_in[5];
    const float* W_lv          = (const float*)d_in[6];
    const float* b_lv          = (const float*)d_in[7];
    float* out = (float*)d_out;

    const int smem_fgemm = 2 * FG_BUF;           // 208896
    const int smem_lv    = 2 * LV_BUF;           // 73728
    const int smem_pg    = 2 * PG_BUF;           // 73728
    cudaFuncSetAttribute(k_fgemm,  cudaFuncAttributeMaxDynamicSharedMemorySize, smem_fgemm);
    cudaFuncSetAttribute(k_lvgemm, cudaFuncAttributeMaxDynamicSharedMemorySize, smem_lv);
    cudaFuncSetAttribute(k_pgemm,  cudaFuncAttributeMaxDynamicSharedMemorySize, smem_pg);

    k_prep<<<5028, 256>>>(train_inputs, test_inputs, W_fe, W_lv,
                          train_targets, test_targets);
    k_fgemm<<<dim3(2, 64, 2), 256, smem_fgemm>>>(b_fe);
    k_lvgemm<<<dim3(18, 8), 256, smem_lv>>>(b_lv);
    k_pgemm<<<dim3(4, 4, PK_SLICES), 256, smem_pg>>>();
    k_softmax<<<NEP, 256>>>(out, out_size);
}